// round 1
// baseline (speedup 1.0000x reference)
#include <cuda_runtime.h>
#include <math.h>

#define PI_F 3.14159265358979323846f

// Fixed problem sizes
// B=8, C=64, H=W=64, K=3, PD=576, SD=128, NQ=6, NL=2

__device__ float g_Ur[4096];   // [s][z] : column s of U, amplitude z (real)
__device__ float g_Ui[4096];   // imag
__device__ float g_style[48];  // [8][6] style angles

// ---------------------------------------------------------------------------
// Setup kernel: build the fixed 64x64 unitary U (HEA + CNOT ring + U3 layer)
// and the per-batch style angles. 1 block, 64 threads (thread t = column t).
// ---------------------------------------------------------------------------
__global__ void qcnn_setup_kernel(const float* __restrict__ style,
                                  const float* __restrict__ s2d_w,
                                  const float* __restrict__ s2d_b,
                                  const float* __restrict__ qcnn,
                                  const float* __restrict__ meas)
{
    int t = threadIdx.x;  // 0..63

    // style_angles[b][j] = tanh(style[b] . s2d_w[j] + b_j) * pi
    if (t < 48) {
        int b = t / 6, j = t - 6 * b;
        float acc = s2d_b[j];
        const float* sp = style + b * 128;
        const float* wp = s2d_w + j * 128;
        #pragma unroll 8
        for (int k = 0; k < 128; k++) acc += sp[k] * wp[k];
        g_style[t] = tanhf(acc) * PI_F;
    }

    // Register-resident column statevector (fully unrolled => static indices)
    float ur[64], ui[64];
    #pragma unroll
    for (int z = 0; z < 64; z++) { ur[z] = (z == t) ? 1.f : 0.f; ui[z] = 0.f; }

    // HEA layers: per-wire RY, RZ; then ring CNOTs. wire i <-> bit (5-i).
    for (int l = 0; l < 2; l++) {
        #pragma unroll
        for (int i = 0; i < 6; i++) {
            const int m = 1 << (5 - i);
            float thy = qcnn[((l * 6 + i) * 2 + 0) * 3 + 0];
            float thz = qcnn[((l * 6 + i) * 2 + 1) * 3 + 0];
            float c, s; sincosf(0.5f * thy, &s, &c);
            #pragma unroll
            for (int z = 0; z < 64; z++) {
                if (!(z & m)) {
                    int z1 = z | m;
                    float r0 = ur[z], i0 = ui[z], r1 = ur[z1], i1 = ui[z1];
                    ur[z]  = c * r0 - s * r1;  ui[z]  = c * i0 - s * i1;
                    ur[z1] = s * r0 + c * r1;  ui[z1] = s * i0 + c * i1;
                }
            }
            float cz, sz; sincosf(0.5f * thz, &sz, &cz);
            #pragma unroll
            for (int z = 0; z < 64; z++) {
                float ph = (z & m) ? sz : -sz;  // e^{+- i thz/2}
                float r = ur[z], im = ui[z];
                ur[z] = cz * r - ph * im;
                ui[z] = cz * im + ph * r;
            }
        }
        #pragma unroll
        for (int i = 0; i < 6; i++) {
            const int mc = 1 << (5 - i);
            const int mt = 1 << (5 - ((i + 1) % 6));
            #pragma unroll
            for (int z = 0; z < 64; z++) {
                if ((z & mc) && !(z & mt)) {
                    int z2 = z | mt;
                    float tr = ur[z], ti = ui[z];
                    ur[z] = ur[z2];  ui[z] = ui[z2];
                    ur[z2] = tr;     ui[z2] = ti;
                }
            }
        }
    }

    // Trainable measurement basis: U3(theta, phi, lam) per wire
    #pragma unroll
    for (int i = 0; i < 6; i++) {
        const int m = 1 << (5 - i);
        float th = meas[i * 3 + 0], ph = meas[i * 3 + 1], la = meas[i * 3 + 2];
        float ct, st; sincosf(0.5f * th, &st, &ct);
        float cl, sl; sincosf(la, &sl, &cl);
        float cp, sp; sincosf(ph, &sp, &cp);
        float cpl, spl; sincosf(ph + la, &spl, &cpl);
        float u01r = -cl * st, u01i = -sl * st;
        float u10r =  cp * st, u10i =  sp * st;
        float u11r = cpl * ct, u11i = spl * ct;
        #pragma unroll
        for (int z = 0; z < 64; z++) {
            if (!(z & m)) {
                int z1 = z | m;
                float r0 = ur[z], i0 = ui[z], r1 = ur[z1], i1 = ui[z1];
                ur[z]  = ct * r0 + u01r * r1 - u01i * i1;
                ui[z]  = ct * i0 + u01r * i1 + u01i * r1;
                ur[z1] = u10r * r0 - u10i * i0 + u11r * r1 - u11i * i1;
                ui[z1] = u10r * i0 + u10i * r0 + u11r * i1 + u11i * r1;
            }
        }
    }

    #pragma unroll
    for (int z = 0; z < 64; z++) {
        g_Ur[t * 64 + z] = ur[z];
        g_Ui[t * 64 + z] = ui[z];
    }
}

// ---------------------------------------------------------------------------
// Main fused kernel. One block per (b, h) image row (64 pixels).
// Phase A: 3x3 conv, 64 in -> 80 padded channels (70 real: 64 res + 6 angles)
//          accumulated with packed fp32x2 FFMA2.
// Phase B: per pixel: tanh -> theta -> product state a[64] -> psi = U a
//          -> Z expvals -> out_proj + residual + biases.
// Shared memory layout (bytes):
//   conv_s [80][64]            : 20480   (persistent)
//   Ws     [576][80]           : 184320  (phase A)   | overlay in phase B:
//   inrow  [64][66]            : 16896   (phase A)   |  Ur 16384, Ui 16384,
//                                                    |  a  16640, e 2304
// total = 221696 B
// ---------------------------------------------------------------------------
#define SMEM_BYTES 221696

__global__ __launch_bounds__(256, 1)
void qcnn_main_kernel(const float* __restrict__ x,
                      const float* __restrict__ dat_w,
                      const float* __restrict__ dat_b,
                      const float* __restrict__ out_w,
                      const float* __restrict__ out_b,
                      const float* __restrict__ res_w,
                      const float* __restrict__ res_b,
                      float* __restrict__ out)
{
    extern __shared__ float sm[];
    float* conv_s = sm;                    // [80][64] channel-major
    float* Ws     = sm + 80 * 64;          // [576][80]
    float* inrow  = Ws + 576 * 80;         // [64][66]
    // Phase-B overlay (inside Ws region)
    float* Urs = Ws;                       // [64][64]  (s-major: Urs[s*64+z])
    float* Uis = Urs + 4096;
    float* a_s = Uis + 4096;               // [64][65]  (padded, conflict-free)
    float* e_s = a_s + 64 * 65;            // [64][9]

    const int tid = threadIdx.x;
    const int bid = blockIdx.x;
    const int b = bid >> 6;
    const int h = bid & 63;

    // --- Stage weights: Ws[k][c] = W[c][k]; c<64 from res_proj, 64..69 data_proj
    for (int idx = tid; idx < 70 * 576; idx += 256) {
        int c = idx / 576;
        int k = idx - c * 576;
        float v = (c < 64) ? res_w[idx] : dat_w[(c - 64) * 576 + k];
        Ws[k * 80 + c] = v;
    }
    for (int idx = tid; idx < 576 * 10; idx += 256) {       // zero pad c=70..79
        int k = idx / 10;
        Ws[k * 80 + 70 + (idx - k * 10)] = 0.f;
    }

    const int w  = tid & 63;     // pixel (column)
    const int cg = tid >> 6;     // channel group: 20 channels at cg*20

    unsigned long long acc[10];
    #pragma unroll
    for (int j = 0; j < 10; j++) acc[j] = 0ULL;

    // --- Phase A: conv. Loop rows dy, stage one padded input row at a time.
    for (int dy = 0; dy < 3; dy++) {
        __syncthreads();
        const int hh = h + dy - 1;
        const bool rowok = (hh >= 0) && (hh < 64);
        for (int idx = tid; idx < 64 * 66; idx += 256) {
            int cin = idx / 66;
            int ww  = idx - cin * 66;
            int gw  = ww - 1;
            float v = 0.f;
            if (rowok && gw >= 0 && gw < 64)
                v = x[(((b * 64 + cin) * 64) + hh) * 64 + gw];
            inrow[idx] = v;
        }
        __syncthreads();

        const int kbase = dy * 3;
        for (int cin = 0; cin < 64; cin++) {
            const float* irow = inrow + cin * 66 + w;
            const float* wrow = Ws + (cin * 9 + kbase) * 80 + cg * 20;
            #pragma unroll
            for (int dx = 0; dx < 3; dx++) {
                float iv = irow[dx];
                unsigned long long iv2;
                asm("mov.b64 %0, {%1, %1};" : "=l"(iv2) : "r"(__float_as_uint(iv)));
                const float* wp = wrow + dx * 80;
                #pragma unroll
                for (int jj = 0; jj < 5; jj++) {
                    ulonglong2 wv = *reinterpret_cast<const ulonglong2*>(wp + jj * 4);
                    asm("fma.rn.f32x2 %0, %1, %2, %0;" : "+l"(acc[2*jj])   : "l"(wv.x), "l"(iv2));
                    asm("fma.rn.f32x2 %0, %1, %2, %0;" : "+l"(acc[2*jj+1]) : "l"(wv.y), "l"(iv2));
                }
            }
        }
    }

    // --- Write conv results (channel-major) ---
    #pragma unroll
    for (int j = 0; j < 10; j++) {
        unsigned int lo = (unsigned int)(acc[j] & 0xffffffffULL);
        unsigned int hi = (unsigned int)(acc[j] >> 32);
        conv_s[(cg * 20 + 2 * j) * 64 + w]     = __uint_as_float(lo);
        conv_s[(cg * 20 + 2 * j + 1) * 64 + w] = __uint_as_float(hi);
    }
    __syncthreads();   // all Ws/inrow readers done -> safe to overlay

    // --- Phase B setup: load U into smem; style/bias to regs ---
    for (int idx = tid; idx < 4096; idx += 256) {
        Urs[idx] = g_Ur[idx];
        Uis[idx] = g_Ui[idx];
    }
    float st6[6], db6[6];
    #pragma unroll
    for (int i = 0; i < 6; i++) { st6[i] = g_style[b * 6 + i]; db6[i] = dat_b[i]; }
    __syncthreads();

    // --- Per pixel: theta -> product state a ---
    const int wq = tid >> 2;    // pixel 0..63
    const int q  = tid & 3;     // quarter: z range [q*16, q*16+16)
    float cc[6], sn[6];
    #pragma unroll
    for (int i = 0; i < 6; i++) {
        float pre = conv_s[(64 + i) * 64 + wq];
        float th = tanhf(pre + db6[i]) * PI_F + st6[i];
        sincosf(0.5f * th, &sn[i], &cc[i]);
    }
    #pragma unroll
    for (int zz = 0; zz < 16; zz++) {
        int z = q * 16 + zz;
        float a = ((z >> 5) & 1) ? sn[0] : cc[0];
        #pragma unroll
        for (int i = 1; i < 6; i++) a *= ((z >> (5 - i)) & 1) ? sn[i] : cc[i];
        a_s[wq * 65 + z] = a;
    }
    __syncthreads();

    // --- psi = U a (two real matvecs), probs, signed reductions ---
    float pr[16], pim[16];
    #pragma unroll
    for (int zz = 0; zz < 16; zz++) { pr[zz] = 0.f; pim[zz] = 0.f; }
    const float* arow = a_s + wq * 65;
    #pragma unroll 8
    for (int s = 0; s < 64; s++) {
        float av = arow[s];
        const float4* u4 = reinterpret_cast<const float4*>(Urs + s * 64 + q * 16);
        const float4* v4 = reinterpret_cast<const float4*>(Uis + s * 64 + q * 16);
        #pragma unroll
        for (int jj = 0; jj < 4; jj++) {
            float4 u = u4[jj];
            float4 v = v4[jj];
            pr[4*jj+0] += u.x * av;  pr[4*jj+1] += u.y * av;
            pr[4*jj+2] += u.z * av;  pr[4*jj+3] += u.w * av;
            pim[4*jj+0] += v.x * av; pim[4*jj+1] += v.y * av;
            pim[4*jj+2] += v.z * av; pim[4*jj+3] += v.w * av;
        }
    }
    float e[6] = {0.f, 0.f, 0.f, 0.f, 0.f, 0.f};
    #pragma unroll
    for (int zz = 0; zz < 16; zz++) {
        int z = q * 16 + zz;
        float p = pr[zz] * pr[zz] + pim[zz] * pim[zz];
        #pragma unroll
        for (int i = 0; i < 6; i++)
            e[i] += ((z >> (5 - i)) & 1) ? -p : p;
    }
    #pragma unroll
    for (int i = 0; i < 6; i++) {
        e[i] += __shfl_xor_sync(0xffffffffu, e[i], 1);
        e[i] += __shfl_xor_sync(0xffffffffu, e[i], 2);
    }
    if (q == 0) {
        #pragma unroll
        for (int i = 0; i < 6; i++) e_s[wq * 9 + i] = e[i];
    }
    __syncthreads();

    // --- Epilogue: out[c] = conv[c] + out_b + res_b + out_w[c,:] . e ---
    const int wo = tid & 63;
    const int cq = tid >> 6;
    float ev[6];
    #pragma unroll
    for (int i = 0; i < 6; i++) ev[i] = e_s[wo * 9 + i];
    #pragma unroll
    for (int j = 0; j < 16; j++) {
        int c = cq * 16 + j;
        float v = conv_s[c * 64 + wo] + out_b[c] + res_b[c];
        #pragma unroll
        for (int i = 0; i < 6; i++) v += out_w[c * 6 + i] * ev[i];
        out[(((long)b * 64 + c) * 64 + h) * 64 + wo] = v;
    }
}

// ---------------------------------------------------------------------------
extern "C" void kernel_launch(void* const* d_in, const int* in_sizes, int n_in,
                              void* d_out, int out_size)
{
    (void)in_sizes; (void)n_in; (void)out_size;
    const float* x      = (const float*)d_in[0];
    const float* style  = (const float*)d_in[1];
    const float* dat_w  = (const float*)d_in[2];
    const float* dat_b  = (const float*)d_in[3];
    const float* s2d_w  = (const float*)d_in[4];
    const float* s2d_b  = (const float*)d_in[5];
    const float* qcnn   = (const float*)d_in[6];
    const float* meas   = (const float*)d_in[7];
    const float* out_w  = (const float*)d_in[8];
    const float* out_b  = (const float*)d_in[9];
    const float* res_w  = (const float*)d_in[10];
    const float* res_b  = (const float*)d_in[11];
    float* out = (float*)d_out;

    cudaFuncSetAttribute(qcnn_main_kernel,
                         cudaFuncAttributeMaxDynamicSharedMemorySize, SMEM_BYTES);

    qcnn_setup_kernel<<<1, 64>>>(style, s2d_w, s2d_b, qcnn, meas);
    qcnn_main_kernel<<<512, 256, SMEM_BYTES>>>(x, dat_w, dat_b, out_w, out_b,
                                               res_w, res_b, out);
}

// round 2
// speedup vs baseline: 1.2311x; 1.2311x over previous
#include <cuda_runtime.h>
#include <math.h>

#define PI_F 3.14159265358979323846f

// Fixed problem sizes: B=8, C=64, H=W=64, K=3, PD=576, SD=128, NQ=6, NL=2

__device__ float g_Ur[4096];   // [s][z] : column s of U, amplitude z (real)
__device__ float g_Ui[4096];   // imag
__device__ float g_style[48];  // [8][6] style angles

// ---------------------------------------------------------------------------
// Setup kernel: build the fixed 64x64 unitary U and per-batch style angles.
// ---------------------------------------------------------------------------
__global__ void qcnn_setup_kernel(const float* __restrict__ style,
                                  const float* __restrict__ s2d_w,
                                  const float* __restrict__ s2d_b,
                                  const float* __restrict__ qcnn,
                                  const float* __restrict__ meas)
{
    int t = threadIdx.x;  // 0..63

    if (t < 48) {
        int b = t / 6, j = t - 6 * b;
        float acc = s2d_b[j];
        const float* sp = style + b * 128;
        const float* wp = s2d_w + j * 128;
        #pragma unroll 8
        for (int k = 0; k < 128; k++) acc += sp[k] * wp[k];
        g_style[t] = tanhf(acc) * PI_F;
    }

    float ur[64], ui[64];
    #pragma unroll
    for (int z = 0; z < 64; z++) { ur[z] = (z == t) ? 1.f : 0.f; ui[z] = 0.f; }

    for (int l = 0; l < 2; l++) {
        #pragma unroll
        for (int i = 0; i < 6; i++) {
            const int m = 1 << (5 - i);
            float thy = qcnn[((l * 6 + i) * 2 + 0) * 3 + 0];
            float thz = qcnn[((l * 6 + i) * 2 + 1) * 3 + 0];
            float c, s; sincosf(0.5f * thy, &s, &c);
            #pragma unroll
            for (int z = 0; z < 64; z++) {
                if (!(z & m)) {
                    int z1 = z | m;
                    float r0 = ur[z], i0 = ui[z], r1 = ur[z1], i1 = ui[z1];
                    ur[z]  = c * r0 - s * r1;  ui[z]  = c * i0 - s * i1;
                    ur[z1] = s * r0 + c * r1;  ui[z1] = s * i0 + c * i1;
                }
            }
            float cz, sz; sincosf(0.5f * thz, &sz, &cz);
            #pragma unroll
            for (int z = 0; z < 64; z++) {
                float ph = (z & m) ? sz : -sz;
                float r = ur[z], im = ui[z];
                ur[z] = cz * r - ph * im;
                ui[z] = cz * im + ph * r;
            }
        }
        #pragma unroll
        for (int i = 0; i < 6; i++) {
            const int mc = 1 << (5 - i);
            const int mt = 1 << (5 - ((i + 1) % 6));
            #pragma unroll
            for (int z = 0; z < 64; z++) {
                if ((z & mc) && !(z & mt)) {
                    int z2 = z | mt;
                    float tr = ur[z], ti = ui[z];
                    ur[z] = ur[z2];  ui[z] = ui[z2];
                    ur[z2] = tr;     ui[z2] = ti;
                }
            }
        }
    }

    #pragma unroll
    for (int i = 0; i < 6; i++) {
        const int m = 1 << (5 - i);
        float th = meas[i * 3 + 0], ph = meas[i * 3 + 1], la = meas[i * 3 + 2];
        float ct, st; sincosf(0.5f * th, &st, &ct);
        float cl, sl; sincosf(la, &sl, &cl);
        float cp, sp; sincosf(ph, &sp, &cp);
        float cpl, spl; sincosf(ph + la, &spl, &cpl);
        float u01r = -cl * st, u01i = -sl * st;
        float u10r =  cp * st, u10i =  sp * st;
        float u11r = cpl * ct, u11i = spl * ct;
        #pragma unroll
        for (int z = 0; z < 64; z++) {
            if (!(z & m)) {
                int z1 = z | m;
                float r0 = ur[z], i0 = ui[z], r1 = ur[z1], i1 = ui[z1];
                ur[z]  = ct * r0 + u01r * r1 - u01i * i1;
                ui[z]  = ct * i0 + u01r * i1 + u01i * r1;
                ur[z1] = u10r * r0 - u10i * i0 + u11r * r1 - u11i * i1;
                ui[z1] = u10r * i0 + u10i * r0 + u11r * i1 + u11i * r1;
            }
        }
    }

    #pragma unroll
    for (int z = 0; z < 64; z++) {
        g_Ur[t * 64 + z] = ur[z];
        g_Ui[t * 64 + z] = ui[z];
    }
}

// ---------------------------------------------------------------------------
// Main fused kernel. 128 blocks (single wave), 640 threads.
// Block = (batch b, 4 consecutive image rows h0..h0+3).
// Phase A: 3x3 conv 64->80 padded channels; thread = (pixel w, 8-ch group cg).
//          Register accumulators acc[4 rows][4 f32x2]; loop over 6 input rows,
//          each feeding up to 3 output rows (dy = r - o).
// Phase B: quantum part per pixel (256 px/block), then epilogue.
// Shared memory (floats):
//   Ws [576][80] = 46080                 | overlay after conv:
//   inrow0/1 [64][66] x2 = 8448         |  conv_s [4][70][66] = 18480
//                                        |  Ur 4096, Ui 4096
//                                        |  a_s [128][65] = 8320
//                                        |  e_s [256][9] = 2304, params ~530
// total = 54528 floats = 218112 B
// ---------------------------------------------------------------------------
#define SMEM_FLOATS (46080 + 2 * 4224)
#define SMEM_BYTES  (SMEM_FLOATS * 4)

#define FMA2(acc, a, b) asm("fma.rn.f32x2 %0, %1, %2, %0;" : "+l"(acc) : "l"(a), "l"(b))
#define DUP2(d, f)      asm("mov.b64 %0, {%1, %1};" : "=l"(d) : "r"(__float_as_uint(f)))

__global__ __launch_bounds__(640, 1)
void qcnn_main_kernel(const float* __restrict__ x,
                      const float* __restrict__ dat_w,
                      const float* __restrict__ dat_b,
                      const float* __restrict__ out_w,
                      const float* __restrict__ out_b,
                      const float* __restrict__ res_w,
                      const float* __restrict__ res_b,
                      float* __restrict__ out)
{
    extern __shared__ float sm[];
    float* Ws     = sm;                    // [576][80]
    float* inrow0 = sm + 46080;            // [64][66]
    float* inrow1 = inrow0 + 4224;
    // Phase-B overlay (inside Ws region)
    float* conv_s = sm;                    // [4][70][66]
    float* Urs    = sm + 18480;            // [64][64]
    float* Uis    = Urs + 4096;
    float* a_s    = Uis + 4096;            // [128][65]
    float* e_s    = a_s + 8320;            // [256][9]
    float* pw     = e_s + 2304;            // out_w [64*6]
    float* pob    = pw + 384;              // out_b [64]
    float* prb    = pob + 64;              // res_b [64]
    float* pst    = prb + 64;              // style[6] @0, dat_b[6] @8

    const int tid = threadIdx.x;
    const int b   = blockIdx.x >> 4;
    const int h0  = (blockIdx.x & 15) << 2;
    const int w   = tid & 63;
    const int cg  = tid >> 6;              // 0..9 (8 channels each)

    // --- Stage weights: Ws[k][c], c<64 res_proj, 64..69 data_proj, 70..79 pad
    for (int idx = tid; idx < 70 * 576; idx += 640) {
        int c = idx / 576;
        int k = idx - c * 576;
        float v = (c < 64) ? res_w[idx] : dat_w[(c - 64) * 576 + k];
        Ws[k * 80 + c] = v;
    }
    for (int idx = tid; idx < 576 * 10; idx += 640) {
        int k = idx / 10;
        Ws[k * 80 + 70 + (idx - k * 10)] = 0.f;
    }
    // --- Stage input row r=0 (global row h0-1) into inrow0
    {
        int hh = h0 - 1;
        bool ok = (hh >= 0);
        for (int idx = tid; idx < 4224; idx += 640) {
            int cin = idx / 66;
            int ww  = idx - cin * 66;
            int gw  = ww - 1;
            float v = 0.f;
            if (ok && gw >= 0 && gw < 64)
                v = x[((b * 64 + cin) * 64 + hh) * 64 + gw];
            inrow0[idx] = v;
        }
    }
    __syncthreads();

    unsigned long long acc[4][4];
    #pragma unroll
    for (int o = 0; o < 4; o++)
        #pragma unroll
        for (int j = 0; j < 4; j++) acc[o][j] = 0ULL;

    const int cg8 = cg * 8;

    // --- Phase A: loop over 6 input rows r (global row h0+r-1) ---
    #pragma unroll
    for (int r = 0; r < 6; r++) {
        float* cur = (r & 1) ? inrow1 : inrow0;
        float* nxt = (r & 1) ? inrow0 : inrow1;
        if (r < 5) {   // prefetch next input row (global row h0+r)
            int hh = h0 + r;
            bool ok = (hh < 64);   // hh >= 0 always here
            for (int idx = tid; idx < 4224; idx += 640) {
                int cin = idx / 66;
                int ww  = idx - cin * 66;
                int gw  = ww - 1;
                float v = 0.f;
                if (ok && gw >= 0 && gw < 64)
                    v = x[((b * 64 + cin) * 64 + hh) * 64 + gw];
                nxt[idx] = v;
            }
        }

        const float* ir = cur + w;
        #pragma unroll 2
        for (int cin = 0; cin < 64; cin++) {
            #pragma unroll
            for (int dx = 0; dx < 3; dx++) {
                float iv = ir[cin * 66 + dx];
                unsigned long long iv2;
                DUP2(iv2, iv);
                #pragma unroll
                for (int o = 0; o < 4; o++) {
                    const int dy = r - o;
                    if (dy >= 0 && dy < 3) {
                        const ulonglong2* wp = reinterpret_cast<const ulonglong2*>(
                            Ws + (cin * 9 + dy * 3 + dx) * 80 + cg8);
                        ulonglong2 wv0 = wp[0];
                        FMA2(acc[o][0], wv0.x, iv2);
                        FMA2(acc[o][1], wv0.y, iv2);
                        ulonglong2 wv1 = wp[1];
                        FMA2(acc[o][2], wv1.x, iv2);
                        FMA2(acc[o][3], wv1.y, iv2);
                    }
                }
            }
        }
        __syncthreads();
    }

    // --- Dump conv results to conv_s [4][70][66]; stage U + params ---
    #pragma unroll
    for (int o = 0; o < 4; o++) {
        #pragma unroll
        for (int jj = 0; jj < 4; jj++) {
            int c0 = cg8 + 2 * jj;
            unsigned int lo = (unsigned int)(acc[o][jj] & 0xffffffffULL);
            unsigned int hi = (unsigned int)(acc[o][jj] >> 32);
            if (c0 < 70)     conv_s[(o * 70 + c0) * 66 + w]     = __uint_as_float(lo);
            if (c0 + 1 < 70) conv_s[(o * 70 + c0 + 1) * 66 + w] = __uint_as_float(hi);
        }
    }
    for (int idx = tid; idx < 4096; idx += 640) {
        Urs[idx] = g_Ur[idx];
        Uis[idx] = g_Ui[idx];
    }
    if (tid < 384) pw[tid] = out_w[tid];
    if (tid >= 384 && tid < 448) { pob[tid - 384] = out_b[tid - 384]; prb[tid - 384] = res_b[tid - 384]; }
    if (tid >= 448 && tid < 454) { pst[tid - 448] = g_style[b * 6 + (tid - 448)]; pst[8 + tid - 448] = dat_b[tid - 448]; }
    __syncthreads();

    // --- Phase B: quantum part. 512 threads = 128 pixels x 4 quarters, x2 ---
    if (tid < 512) {
        const int q  = tid & 3;
        const int p2 = tid >> 2;   // 0..127
        #pragma unroll
        for (int it = 0; it < 2; it++) {
            const int p  = it * 128 + p2;     // pixel 0..255
            const int o  = p >> 6;
            const int wq = p & 63;

            float cc[6], sn[6];
            #pragma unroll
            for (int i = 0; i < 6; i++) {
                float pre = conv_s[(o * 70 + 64 + i) * 66 + wq];
                float th = tanhf(pre + pst[8 + i]) * PI_F + pst[i];
                sincosf(0.5f * th, &sn[i], &cc[i]);
            }
            #pragma unroll
            for (int zz = 0; zz < 16; zz++) {
                int z = q * 16 + zz;
                float a = ((z >> 5) & 1) ? sn[0] : cc[0];
                #pragma unroll
                for (int i = 1; i < 6; i++) a *= ((z >> (5 - i)) & 1) ? sn[i] : cc[i];
                a_s[p2 * 65 + z] = a;
            }
            __syncwarp();

            unsigned long long prx[8], pix8[8];
            #pragma unroll
            for (int k = 0; k < 8; k++) { prx[k] = 0ULL; pix8[k] = 0ULL; }
            const float* arow = a_s + p2 * 65;
            #pragma unroll 8
            for (int s = 0; s < 64; s++) {
                float av = arow[s];
                unsigned long long av2;
                DUP2(av2, av);
                const ulonglong2* u2 = reinterpret_cast<const ulonglong2*>(Urs + s * 64 + q * 16);
                const ulonglong2* v2 = reinterpret_cast<const ulonglong2*>(Uis + s * 64 + q * 16);
                #pragma unroll
                for (int j = 0; j < 4; j++) {
                    ulonglong2 uu = u2[j];
                    ulonglong2 vv = v2[j];
                    FMA2(prx[2 * j],      uu.x, av2);
                    FMA2(prx[2 * j + 1],  uu.y, av2);
                    FMA2(pix8[2 * j],     vv.x, av2);
                    FMA2(pix8[2 * j + 1], vv.y, av2);
                }
            }

            // probs + expvals; z = q*16 + t, t = 2k{+1}. bit5=q>>1, bit4=q&1,
            // bits3..0 = t (compile-time per k).
            float psum = 0.f, e2 = 0.f, e3 = 0.f, e4 = 0.f, e5 = 0.f;
            #pragma unroll
            for (int k = 0; k < 8; k++) {
                unsigned int rlo, rhi, ilo, ihi;
                asm("mov.b64 {%0,%1}, %2;" : "=r"(rlo), "=r"(rhi) : "l"(prx[k]));
                asm("mov.b64 {%0,%1}, %2;" : "=r"(ilo), "=r"(ihi) : "l"(pix8[k]));
                float r0 = __uint_as_float(rlo), r1 = __uint_as_float(rhi);
                float i0 = __uint_as_float(ilo), i1 = __uint_as_float(ihi);
                float p0 = r0 * r0 + i0 * i0;
                float p1 = r1 * r1 + i1 * i1;
                const int t0 = 2 * k;
                psum += p0 + p1;
                e2 += ((t0 >> 3) & 1) ? -(p0 + p1) : (p0 + p1);
                e3 += ((t0 >> 2) & 1) ? -(p0 + p1) : (p0 + p1);
                e4 += ((t0 >> 1) & 1) ? -(p0 + p1) : (p0 + p1);
                e5 += p0 - p1;
            }
            float e[6];
            e[0] = (q & 2) ? -psum : psum;
            e[1] = (q & 1) ? -psum : psum;
            e[2] = e2; e[3] = e3; e[4] = e4; e[5] = e5;
            #pragma unroll
            for (int i = 0; i < 6; i++) {
                e[i] += __shfl_xor_sync(0xffffffffu, e[i], 1);
                e[i] += __shfl_xor_sync(0xffffffffu, e[i], 2);
            }
            if (q == 0) {
                #pragma unroll
                for (int i = 0; i < 6; i++) e_s[p * 9 + i] = e[i];
            }
            __syncwarp();
        }
    }
    __syncthreads();

    // --- Epilogue: 512 threads = (pixel w, 8-ch group), 4 rows each ---
    if (tid < 512) {
        const int wE  = tid & 63;
        const int cgE = tid >> 6;     // 0..7
        #pragma unroll
        for (int o = 0; o < 4; o++) {
            float ev[6];
            #pragma unroll
            for (int i = 0; i < 6; i++) ev[i] = e_s[(o * 64 + wE) * 9 + i];
            #pragma unroll
            for (int j = 0; j < 8; j++) {
                int c = cgE * 8 + j;
                float v = conv_s[(o * 70 + c) * 66 + wE] + pob[c] + prb[c];
                #pragma unroll
                for (int i = 0; i < 6; i++) v += pw[c * 6 + i] * ev[i];
                out[((b * 64 + c) * 64 + (h0 + o)) * 64 + wE] = v;
            }
        }
    }
}

// ---------------------------------------------------------------------------
extern "C" void kernel_launch(void* const* d_in, const int* in_sizes, int n_in,
                              void* d_out, int out_size)
{
    (void)in_sizes; (void)n_in; (void)out_size;
    const float* x      = (const float*)d_in[0];
    const float* style  = (const float*)d_in[1];
    const float* dat_w  = (const float*)d_in[2];
    const float* dat_b  = (const float*)d_in[3];
    const float* s2d_w  = (const float*)d_in[4];
    const float* s2d_b  = (const float*)d_in[5];
    const float* qcnn   = (const float*)d_in[6];
    const float* meas   = (const float*)d_in[7];
    const float* out_w  = (const float*)d_in[8];
    const float* out_b  = (const float*)d_in[9];
    const float* res_w  = (const float*)d_in[10];
    const float* res_b  = (const float*)d_in[11];
    float* out = (float*)d_out;

    cudaFuncSetAttribute(qcnn_main_kernel,
                         cudaFuncAttributeMaxDynamicSharedMemorySize, SMEM_BYTES);

    qcnn_setup_kernel<<<1, 64>>>(style, s2d_w, s2d_b, qcnn, meas);
    qcnn_main_kernel<<<128, 640, SMEM_BYTES>>>(x, dat_w, dat_b, out_w, out_b,
                                               res_w, res_b, out);
}

// round 3
// speedup vs baseline: 1.7154x; 1.3934x over previous
#include <cuda_runtime.h>
#include <math.h>

#define PI_F 3.14159265358979323846f

// Fixed problem sizes: B=8, C=64, H=W=64, K=3, PD=576, SD=128, NQ=6, NL=2

__device__ float g_Ur[4096];   // [s][z] : column s of U, amplitude z (real)
__device__ float g_Ui[4096];   // imag
__device__ float g_style[48];  // [8][6] style angles

// ---------------------------------------------------------------------------
// Setup kernel v2: 256 threads. Column c = tid>>2 (4 threads per column),
// each thread owns 16 amplitudes z = q*16 + zz (q = tid&3) in registers.
// Wires 2..5 act within a thread; wires 0 (bit5) / 1 (bit4) act across
// shfl.xor 2 / 1. No register spills.
// ---------------------------------------------------------------------------
__global__ void qcnn_setup_kernel(const float* __restrict__ style,
                                  const float* __restrict__ s2d_w,
                                  const float* __restrict__ s2d_b,
                                  const float* __restrict__ qcnn,
                                  const float* __restrict__ meas)
{
    const int tid = threadIdx.x;  // 0..255

    if (tid < 48) {
        int b = tid / 6, j = tid - 6 * b;
        float acc = s2d_b[j];
        const float* sp = style + b * 128;
        const float* wp = s2d_w + j * 128;
        #pragma unroll 8
        for (int k = 0; k < 128; k++) acc += sp[k] * wp[k];
        g_style[tid] = tanhf(acc) * PI_F;
    }

    const int c = tid >> 2;
    const int q = tid & 3;
    const unsigned FULL = 0xffffffffu;

    float ur[16], ui[16];
    #pragma unroll
    for (int zz = 0; zz < 16; zz++) {
        ur[zz] = (c == q * 16 + zz) ? 1.f : 0.f;
        ui[zz] = 0.f;
    }

    // --- HEA layers ---
    for (int l = 0; l < 2; l++) {
        #pragma unroll
        for (int i = 0; i < 6; i++) {
            const int m = 1 << (5 - i);
            float thy = qcnn[((l * 6 + i) * 2 + 0) * 3 + 0];
            float thz = qcnn[((l * 6 + i) * 2 + 1) * 3 + 0];
            float cy, sy; sincosf(0.5f * thy, &sy, &cy);
            // RY
            if (m < 16) {
                #pragma unroll
                for (int zz = 0; zz < 16; zz++) {
                    if (!(zz & m)) {
                        int z1 = zz | m;
                        float r0 = ur[zz], i0 = ui[zz], r1 = ur[z1], i1 = ui[z1];
                        ur[zz] = cy * r0 - sy * r1;  ui[zz] = cy * i0 - sy * i1;
                        ur[z1] = sy * r0 + cy * r1;  ui[z1] = sy * i0 + cy * i1;
                    }
                }
            } else {
                const int lane = m >> 4;            // 1 for bit4, 2 for bit5
                const int bitv = (q * 16 & m) ? 1 : 0;
                #pragma unroll
                for (int zz = 0; zz < 16; zz++) {
                    float pr = __shfl_xor_sync(FULL, ur[zz], lane);
                    float pi = __shfl_xor_sync(FULL, ui[zz], lane);
                    if (bitv == 0) {
                        ur[zz] = cy * ur[zz] - sy * pr;
                        ui[zz] = cy * ui[zz] - sy * pi;
                    } else {
                        ur[zz] = sy * pr + cy * ur[zz];
                        ui[zz] = sy * pi + cy * ui[zz];
                    }
                }
            }
            // RZ (diagonal)
            float cz, sz; sincosf(0.5f * thz, &sz, &cz);
            #pragma unroll
            for (int zz = 0; zz < 16; zz++) {
                int z = q * 16 + zz;
                float ph = (z & m) ? sz : -sz;
                float r = ur[zz], im = ui[zz];
                ur[zz] = cz * r - ph * im;
                ui[zz] = cz * im + ph * r;
            }
        }
        // ring CNOTs
        #pragma unroll
        for (int i = 0; i < 6; i++) {
            const int mc = 1 << (5 - i);
            const int mt = 1 << (5 - ((i + 1) % 6));
            if (mt < 16) {
                #pragma unroll
                for (int zz = 0; zz < 16; zz++) {
                    int z = q * 16 + zz;
                    if ((z & mc) && !(zz & mt)) {
                        int z2 = zz | mt;
                        float tr = ur[zz], ti = ui[zz];
                        ur[zz] = ur[z2];  ui[zz] = ui[z2];
                        ur[z2] = tr;      ui[z2] = ti;
                    }
                }
            } else {
                const int lane = mt >> 4;
                #pragma unroll
                for (int zz = 0; zz < 16; zz++) {
                    float pr = __shfl_xor_sync(FULL, ur[zz], lane);
                    float pi = __shfl_xor_sync(FULL, ui[zz], lane);
                    int z = q * 16 + zz;
                    if (z & mc) { ur[zz] = pr; ui[zz] = pi; }
                }
            }
        }
    }

    // --- measurement U3 per wire ---
    #pragma unroll
    for (int i = 0; i < 6; i++) {
        const int m = 1 << (5 - i);
        float th = meas[i * 3 + 0], ph = meas[i * 3 + 1], la = meas[i * 3 + 2];
        float ct, st; sincosf(0.5f * th, &st, &ct);
        float cl, sl; sincosf(la, &sl, &cl);
        float cp, sp; sincosf(ph, &sp, &cp);
        float cpl, spl; sincosf(ph + la, &spl, &cpl);
        float u01r = -cl * st, u01i = -sl * st;
        float u10r =  cp * st, u10i =  sp * st;
        float u11r = cpl * ct, u11i = spl * ct;
        if (m < 16) {
            #pragma unroll
            for (int zz = 0; zz < 16; zz++) {
                if (!(zz & m)) {
                    int z1 = zz | m;
                    float r0 = ur[zz], i0 = ui[zz], r1 = ur[z1], i1 = ui[z1];
                    ur[zz] = ct * r0 + u01r * r1 - u01i * i1;
                    ui[zz] = ct * i0 + u01r * i1 + u01i * r1;
                    ur[z1] = u10r * r0 - u10i * i0 + u11r * r1 - u11i * i1;
                    ui[z1] = u10r * i0 + u10i * r0 + u11r * i1 + u11i * r1;
                }
            }
        } else {
            const int lane = m >> 4;
            const int bitv = (q * 16 & m) ? 1 : 0;
            #pragma unroll
            for (int zz = 0; zz < 16; zz++) {
                float pr = __shfl_xor_sync(FULL, ur[zz], lane);
                float pi = __shfl_xor_sync(FULL, ui[zz], lane);
                float r0 = ur[zz], i0 = ui[zz];
                if (bitv == 0) {
                    ur[zz] = ct * r0 + u01r * pr - u01i * pi;
                    ui[zz] = ct * i0 + u01r * pi + u01i * pr;
                } else {
                    ur[zz] = u10r * pr - u10i * pi + u11r * r0 - u11i * i0;
                    ui[zz] = u10r * pi + u10i * pr + u11r * i0 + u11i * r0;
                }
            }
        }
    }

    #pragma unroll
    for (int zz = 0; zz < 16; zz++) {
        g_Ur[c * 64 + q * 16 + zz] = ur[zz];
        g_Ui[c * 64 + q * 16 + zz] = ui[zz];
    }
}

// ---------------------------------------------------------------------------
// Main fused kernel. 128 blocks (single wave), 640 threads.
// Block = (batch b, 4 consecutive image rows h0..h0+3).
// Phase A: 3x3 conv 64->80 padded channels. All 6 input rows resident for a
//          16-cin quarter; each weight vector loaded ONCE feeds 16 FMA2
//          (4 output rows). Register accumulators acc[4][4] (f32x2).
// Phase B: quantum part per pixel, then epilogue.
// Shared memory (floats):
//   Ws [576][80] = 46080                | overlay after conv:
//   inbuf [6][16][66] = 6336            |  conv_s [4][70][66] = 18480
//                                       |  Ur 4096, Ui 4096, a_s 8320
//                                       |  e_s 2304, params ~530
// total = 52416 floats = 209664 B
// ---------------------------------------------------------------------------
#define SMEM_FLOATS (46080 + 6336)
#define SMEM_BYTES  (SMEM_FLOATS * 4)

#define FMA2(acc, a, b) asm("fma.rn.f32x2 %0, %1, %2, %0;" : "+l"(acc) : "l"(a), "l"(b))
#define DUP2(d, f)      asm("mov.b64 %0, {%1, %1};" : "=l"(d) : "r"(__float_as_uint(f)))

__global__ __launch_bounds__(640, 1)
void qcnn_main_kernel(const float* __restrict__ x,
                      const float* __restrict__ dat_w,
                      const float* __restrict__ dat_b,
                      const float* __restrict__ out_w,
                      const float* __restrict__ out_b,
                      const float* __restrict__ res_w,
                      const float* __restrict__ res_b,
                      float* __restrict__ out)
{
    extern __shared__ float sm[];
    float* Ws    = sm;                    // [576][80]
    float* inbuf = sm + 46080;            // [6][16][66]
    // Phase-B overlay (inside Ws region)
    float* conv_s = sm;                   // [4][70][66]
    float* Urs    = sm + 18480;           // [64][64]
    float* Uis    = Urs + 4096;
    float* a_s    = Uis + 4096;           // [128][65]
    float* e_s    = a_s + 8320;           // [256][9]
    float* pw     = e_s + 2304;           // out_w [64*6]
    float* pob    = pw + 384;             // out_b [64]
    float* prb    = pob + 64;             // res_b [64]
    float* pst    = prb + 64;             // style[6] @0, dat_b[6] @8

    const int tid = threadIdx.x;
    const int b   = blockIdx.x >> 4;
    const int h0  = (blockIdx.x & 15) << 2;
    const int w   = tid & 63;
    const int cg  = tid >> 6;              // 0..9 (8 channels each)
    const int cg8 = cg * 8;

    // --- Stage weights: Ws[k][c], c<64 res_proj, 64..69 data_proj, 70..79 pad
    for (int idx = tid; idx < 70 * 576; idx += 640) {
        int c = idx / 576;
        int k = idx - c * 576;
        float v = (c < 64) ? res_w[idx] : dat_w[(c - 64) * 576 + k];
        Ws[k * 80 + c] = v;
    }
    for (int idx = tid; idx < 576 * 10; idx += 640) {
        int k = idx / 10;
        Ws[k * 80 + 70 + (idx - k * 10)] = 0.f;
    }

    unsigned long long acc[4][4];
    #pragma unroll
    for (int o = 0; o < 4; o++)
        #pragma unroll
        for (int j = 0; j < 4; j++) acc[o][j] = 0ULL;

    // --- Phase A: 4 quarters of 16 input channels ---
    for (int phq = 0; phq < 4; phq++) {
        __syncthreads();   // previous quarter's readers done / weights staged
        // stage 6 rows x 16 cin x 66 (padded)
        for (int idx = tid; idx < 6336; idx += 640) {
            int r   = idx / 1056;
            int rem = idx - r * 1056;
            int ci  = rem / 66;
            int ww  = rem - ci * 66;
            int hh  = h0 + r - 1;
            int gw  = ww - 1;
            float v = 0.f;
            if (hh >= 0 && hh < 64 && gw >= 0 && gw < 64)
                v = x[((b * 64 + phq * 16 + ci) * 64 + hh) * 64 + gw];
            inbuf[idx] = v;
        }
        __syncthreads();

        const float* ib    = inbuf + w;
        const float* wbase = Ws + (phq * 16) * 9 * 80 + cg8;
        #pragma unroll 2
        for (int ci = 0; ci < 16; ci++) {
            #pragma unroll
            for (int dx = 0; dx < 3; dx++) {
                unsigned long long iv2[6];
                #pragma unroll
                for (int r = 0; r < 6; r++) {
                    float iv = ib[(r * 16 + ci) * 66 + dx];
                    DUP2(iv2[r], iv);
                }
                #pragma unroll
                for (int dy = 0; dy < 3; dy++) {
                    const ulonglong2* wp = reinterpret_cast<const ulonglong2*>(
                        wbase + (ci * 9 + dy * 3 + dx) * 80);
                    ulonglong2 wv0 = wp[0];
                    ulonglong2 wv1 = wp[1];
                    #pragma unroll
                    for (int o = 0; o < 4; o++) {
                        FMA2(acc[o][0], wv0.x, iv2[dy + o]);
                        FMA2(acc[o][1], wv0.y, iv2[dy + o]);
                        FMA2(acc[o][2], wv1.x, iv2[dy + o]);
                        FMA2(acc[o][3], wv1.y, iv2[dy + o]);
                    }
                }
            }
        }
    }
    __syncthreads();   // all Ws/inbuf readers done -> safe to overlay

    // --- Dump conv results to conv_s [4][70][66]; stage U + params ---
    #pragma unroll
    for (int o = 0; o < 4; o++) {
        #pragma unroll
        for (int jj = 0; jj < 4; jj++) {
            int c0 = cg8 + 2 * jj;
            unsigned int lo = (unsigned int)(acc[o][jj] & 0xffffffffULL);
            unsigned int hi = (unsigned int)(acc[o][jj] >> 32);
            if (c0 < 70)     conv_s[(o * 70 + c0) * 66 + w]     = __uint_as_float(lo);
            if (c0 + 1 < 70) conv_s[(o * 70 + c0 + 1) * 66 + w] = __uint_as_float(hi);
        }
    }
    for (int idx = tid; idx < 4096; idx += 640) {
        Urs[idx] = g_Ur[idx];
        Uis[idx] = g_Ui[idx];
    }
    if (tid < 384) pw[tid] = out_w[tid];
    if (tid >= 384 && tid < 448) { pob[tid - 384] = out_b[tid - 384]; prb[tid - 384] = res_b[tid - 384]; }
    if (tid >= 448 && tid < 454) { pst[tid - 448] = g_style[b * 6 + (tid - 448)]; pst[8 + tid - 448] = dat_b[tid - 448]; }
    __syncthreads();

    // --- Phase B: quantum part. 512 threads = 128 pixels x 4 quarters, x2 ---
    if (tid < 512) {
        const int q  = tid & 3;
        const int p2 = tid >> 2;   // 0..127
        #pragma unroll
        for (int it = 0; it < 2; it++) {
            const int p  = it * 128 + p2;     // pixel 0..255
            const int o  = p >> 6;
            const int wq = p & 63;

            float cc[6], sn[6];
            #pragma unroll
            for (int i = 0; i < 6; i++) {
                float pre = conv_s[(o * 70 + 64 + i) * 66 + wq];
                float th = tanhf(pre + pst[8 + i]) * PI_F + pst[i];
                sincosf(0.5f * th, &sn[i], &cc[i]);
            }
            #pragma unroll
            for (int zz = 0; zz < 16; zz++) {
                int z = q * 16 + zz;
                float a = ((z >> 5) & 1) ? sn[0] : cc[0];
                #pragma unroll
                for (int i = 1; i < 6; i++) a *= ((z >> (5 - i)) & 1) ? sn[i] : cc[i];
                a_s[p2 * 65 + z] = a;
            }
            __syncwarp();

            unsigned long long prx[8], pix8[8];
            #pragma unroll
            for (int k = 0; k < 8; k++) { prx[k] = 0ULL; pix8[k] = 0ULL; }
            const float* arow = a_s + p2 * 65;
            #pragma unroll 8
            for (int s = 0; s < 64; s++) {
                float av = arow[s];
                unsigned long long av2;
                DUP2(av2, av);
                const ulonglong2* u2 = reinterpret_cast<const ulonglong2*>(Urs + s * 64 + q * 16);
                const ulonglong2* v2 = reinterpret_cast<const ulonglong2*>(Uis + s * 64 + q * 16);
                #pragma unroll
                for (int j = 0; j < 4; j++) {
                    ulonglong2 uu = u2[j];
                    ulonglong2 vv = v2[j];
                    FMA2(prx[2 * j],      uu.x, av2);
                    FMA2(prx[2 * j + 1],  uu.y, av2);
                    FMA2(pix8[2 * j],     vv.x, av2);
                    FMA2(pix8[2 * j + 1], vv.y, av2);
                }
            }

            // probs + expvals; z = q*16 + t: bit5=q>>1, bit4=q&1, bits3..0=t.
            float psum = 0.f, e2 = 0.f, e3 = 0.f, e4 = 0.f, e5 = 0.f;
            #pragma unroll
            for (int k = 0; k < 8; k++) {
                unsigned int rlo, rhi, ilo, ihi;
                asm("mov.b64 {%0,%1}, %2;" : "=r"(rlo), "=r"(rhi) : "l"(prx[k]));
                asm("mov.b64 {%0,%1}, %2;" : "=r"(ilo), "=r"(ihi) : "l"(pix8[k]));
                float r0 = __uint_as_float(rlo), r1 = __uint_as_float(rhi);
                float i0 = __uint_as_float(ilo), i1 = __uint_as_float(ihi);
                float p0 = r0 * r0 + i0 * i0;
                float p1 = r1 * r1 + i1 * i1;
                const int t0 = 2 * k;
                psum += p0 + p1;
                e2 += ((t0 >> 3) & 1) ? -(p0 + p1) : (p0 + p1);
                e3 += ((t0 >> 2) & 1) ? -(p0 + p1) : (p0 + p1);
                e4 += ((t0 >> 1) & 1) ? -(p0 + p1) : (p0 + p1);
                e5 += p0 - p1;
            }
            float e[6];
            e[0] = (q & 2) ? -psum : psum;
            e[1] = (q & 1) ? -psum : psum;
            e[2] = e2; e[3] = e3; e[4] = e4; e[5] = e5;
            #pragma unroll
            for (int i = 0; i < 6; i++) {
                e[i] += __shfl_xor_sync(0xffffffffu, e[i], 1);
                e[i] += __shfl_xor_sync(0xffffffffu, e[i], 2);
            }
            if (q == 0) {
                #pragma unroll
                for (int i = 0; i < 6; i++) e_s[p * 9 + i] = e[i];
            }
            __syncwarp();
        }
    }
    __syncthreads();

    // --- Epilogue: 512 threads = (pixel w, 8-ch group), 4 rows each ---
    if (tid < 512) {
        const int wE  = tid & 63;
        const int cgE = tid >> 6;     // 0..7
        #pragma unroll
        for (int o = 0; o < 4; o++) {
            float ev[6];
            #pragma unroll
            for (int i = 0; i < 6; i++) ev[i] = e_s[(o * 64 + wE) * 9 + i];
            #pragma unroll
            for (int j = 0; j < 8; j++) {
                int c = cgE * 8 + j;
                float v = conv_s[(o * 70 + c) * 66 + wE] + pob[c] + prb[c];
                #pragma unroll
                for (int i = 0; i < 6; i++) v += pw[c * 6 + i] * ev[i];
                out[((b * 64 + c) * 64 + (h0 + o)) * 64 + wE] = v;
            }
        }
    }
}

// ---------------------------------------------------------------------------
extern "C" void kernel_launch(void* const* d_in, const int* in_sizes, int n_in,
                              void* d_out, int out_size)
{
    (void)in_sizes; (void)n_in; (void)out_size;
    const float* x      = (const float*)d_in[0];
    const float* style  = (const float*)d_in[1];
    const float* dat_w  = (const float*)d_in[2];
    const float* dat_b  = (const float*)d_in[3];
    const float* s2d_w  = (const float*)d_in[4];
    const float* s2d_b  = (const float*)d_in[5];
    const float* qcnn   = (const float*)d_in[6];
    const float* meas   = (const float*)d_in[7];
    const float* out_w  = (const float*)d_in[8];
    const float* out_b  = (const float*)d_in[9];
    const float* res_w  = (const float*)d_in[10];
    const float* res_b  = (const float*)d_in[11];
    float* out = (float*)d_out;

    cudaFuncSetAttribute(qcnn_main_kernel,
                         cudaFuncAttributeMaxDynamicSharedMemorySize, SMEM_BYTES);

    qcnn_setup_kernel<<<1, 256>>>(style, s2d_w, s2d_b, qcnn, meas);
    qcnn_main_kernel<<<128, 640, SMEM_BYTES>>>(x, dat_w, dat_b, out_w, out_b,
                                               res_w, res_b, out);
}